// round 6
// baseline (speedup 1.0000x reference)
#include <cuda_runtime.h>
#include <stdint.h>
#include <math.h>

#define N_NODES 50000
#define N_EDGES 500000
#define DIM     128
#define N_REL   51
#define KDIM    1664   // 13*128
#define BK      16
#define NKT     (KDIM / BK)   // 104
#define ASTR    24
#define BSTR    136
#define NGRP    6250           // N_NODES / 8

// ---------------- scratch (device globals; no allocation allowed) ----------
__device__ int   g_deg[N_NODES];
__device__ int   g_off[N_NODES + 1];
__device__ int   g_fill[N_NODES];
__device__ int   g_epk[N_EDGES];      // packed src | (type<<17)
__device__ float g_ew[N_EDGES];
__device__ float g_scaleS[N_NODES];
__device__ float g_x[N_NODES * DIM];
__device__ float g_feats[4 * N_NODES * DIM];   // [feat(4)][node][dim]
__device__ float g_W[4 * KDIM * DIM];          // tf32-rounded weights

// ---------------- helpers ----------------------------------------------------
__device__ __forceinline__ float f2tf(float f) {
    uint32_t u;
    asm("cvt.rna.tf32.f32 %0, %1;" : "=r"(u) : "f"(f));
    return __uint_as_float(u);
}

// ---------------- preprocessing kernels ------------------------------------
__global__ void k_cvtW(const float* __restrict__ linw) {
    int i = blockIdx.x * blockDim.x + threadIdx.x;
    if (i < 4 * KDIM * DIM) g_W[i] = f2tf(linw[i]);
}

__global__ void k_hist(const int* __restrict__ edst) {
    int e = blockIdx.x * blockDim.x + threadIdx.x;
    if (e < N_EDGES) atomicAdd(&g_deg[edst[e]], 1);
}

// single block, 1024 threads; 8 elements per thread per chunk.
// exclusive scan -> g_off/g_fill, plus log-degree scale.
__global__ void k_scan() {
    __shared__ int   wsum[32];
    __shared__ int   carry_sh;
    __shared__ float fred[32];
    __shared__ float ssum_sh;
    int tid  = threadIdx.x;
    int lane = tid & 31, wid = tid >> 5;
    if (tid == 0) carry_sh = 0;
    __syncthreads();

    float ls = 0.0f;

#pragma unroll 1
    for (int c = 0; c < 7; c++) {
        int g = c * 1024 + tid;           // group of 8 elements
        int v[8];
        int tsum = 0;
        if (g < NGRP) {
            int4 a = *reinterpret_cast<const int4*>(g_deg + g * 8);
            int4 b = *reinterpret_cast<const int4*>(g_deg + g * 8 + 4);
            v[0] = a.x; v[1] = a.y; v[2] = a.z; v[3] = a.w;
            v[4] = b.x; v[5] = b.y; v[6] = b.z; v[7] = b.w;
#pragma unroll
            for (int j = 0; j < 8; j++) tsum += v[j];
        } else {
#pragma unroll
            for (int j = 0; j < 8; j++) v[j] = 0;
        }
        // warp inclusive scan of tsum
        int x = tsum;
#pragma unroll
        for (int off = 1; off < 32; off <<= 1) {
            int y = __shfl_up_sync(0xffffffffu, x, off);
            if (lane >= off) x += y;
        }
        if (lane == 31) wsum[wid] = x;
        __syncthreads();
        if (wid == 0) {
            int w = wsum[lane];
#pragma unroll
            for (int off = 1; off < 32; off <<= 1) {
                int y = __shfl_up_sync(0xffffffffu, w, off);
                if (lane >= off) w += y;
            }
            wsum[lane] = w;
        }
        __syncthreads();
        int wpre = (wid > 0) ? wsum[wid - 1] : 0;
        int excl = carry_sh + wpre + x - tsum;
        if (g < NGRP) {
            int run = excl;
#pragma unroll
            for (int j = 0; j < 8; j++) {
                g_off[g * 8 + j]  = run;
                g_fill[g * 8 + j] = run;
                run += v[j];
                ls += logf((float)v[j] + 1.0f);
            }
        }
        __syncthreads();
        if (tid == 1023) carry_sh += wsum[31];
        __syncthreads();
    }
    if (tid == 0) g_off[N_NODES] = N_EDGES;

    // block-reduce log sum
#pragma unroll
    for (int m = 16; m > 0; m >>= 1) ls += __shfl_xor_sync(0xffffffffu, ls, m);
    if (lane == 0) fred[wid] = ls;
    __syncthreads();
    if (wid == 0) {
        float s = fred[lane];
#pragma unroll
        for (int m = 16; m > 0; m >>= 1) s += __shfl_xor_sync(0xffffffffu, s, m);
        if (lane == 0) ssum_sh = s;
    }
    __syncthreads();
    float inv_mean = (float)N_NODES / ssum_sh;

    // scale pass (vectorized)
#pragma unroll 1
    for (int g = tid; g < NGRP; g += 1024) {
        int4 a = *reinterpret_cast<const int4*>(g_deg + g * 8);
        int4 b = *reinterpret_cast<const int4*>(g_deg + g * 8 + 4);
        float4 o0, o1;
        o0.x = logf((float)a.x + 1.0f) * inv_mean;
        o0.y = logf((float)a.y + 1.0f) * inv_mean;
        o0.z = logf((float)a.z + 1.0f) * inv_mean;
        o0.w = logf((float)a.w + 1.0f) * inv_mean;
        o1.x = logf((float)b.x + 1.0f) * inv_mean;
        o1.y = logf((float)b.y + 1.0f) * inv_mean;
        o1.z = logf((float)b.z + 1.0f) * inv_mean;
        o1.w = logf((float)b.w + 1.0f) * inv_mean;
        *reinterpret_cast<float4*>(g_scaleS + g * 8)     = o0;
        *reinterpret_cast<float4*>(g_scaleS + g * 8 + 4) = o1;
    }
}

__global__ void k_fill(const int* __restrict__ esrc, const int* __restrict__ edst,
                       const int* __restrict__ etype, const float* __restrict__ ew) {
    int e = blockIdx.x * blockDim.x + threadIdx.x;
    if (e >= N_EDGES) return;
    int d = edst[e];
    int p = atomicAdd(&g_fill[d], 1);
    g_epk[p] = esrc[e] | (etype[e] << 17);
    g_ew[p]  = ew[e];
}

// ---------------- per-layer aggregation (warp per node) --------------------
// metadata loaded 32 edges at a time (coalesced), broadcast via shfl.
__global__ void k_agg(const float* __restrict__ xin, const float* __restrict__ x0,
                      const float* __restrict__ relw) {
    int gw   = (blockIdx.x * blockDim.x + threadIdx.x) >> 5;
    int lane = threadIdx.x & 31;
    if (gw >= N_NODES) return;
    int beg = g_off[gw], end = g_off[gw + 1];

    float4 vs  = make_float4(0.f, 0.f, 0.f, 0.f);
    float4 vq  = make_float4(0.f, 0.f, 0.f, 0.f);
    float4 vmx = make_float4(-INFINITY, -INFINITY, -INFINITY, -INFINITY);
    float4 vmn = make_float4( INFINITY,  INFINITY,  INFINITY,  INFINITY);

    const float4* xv = reinterpret_cast<const float4*>(xin);
    const float4* rv = reinterpret_cast<const float4*>(relw);

    for (int base = beg; base < end; base += 32) {
        int rem = end - base;
        int n = rem < 32 ? rem : 32;
        int   pk = 0;
        float wv = 0.0f;
        if (lane < n) {
            pk = __ldg(g_epk + base + lane);
            wv = __ldg(g_ew + base + lane);
        }
#pragma unroll 4
        for (int i = 0; i < n; i++) {
            int   pki = __shfl_sync(0xffffffffu, pk, i);
            float w   = __shfl_sync(0xffffffffu, wv, i);
            int s = pki & 0x1FFFF;
            int t = pki >> 17;
            float4 a = __ldg(xv + s * 32 + lane);
            float4 r = __ldg(rv + t * 32 + lane);
            float mx = a.x * r.x * w, my = a.y * r.y * w;
            float mz = a.z * r.z * w, mw = a.w * r.w * w;
            vs.x += mx; vs.y += my; vs.z += mz; vs.w += mw;
            vq.x += mx * mx; vq.y += my * my; vq.z += mz * mz; vq.w += mw * mw;
            vmx.x = fmaxf(vmx.x, mx); vmx.y = fmaxf(vmx.y, my);
            vmx.z = fmaxf(vmx.z, mz); vmx.w = fmaxf(vmx.w, mw);
            vmn.x = fminf(vmn.x, mx); vmn.y = fminf(vmn.y, my);
            vmn.z = fminf(vmn.z, mz); vmn.w = fminf(vmn.w, mw);
        }
    }

    float4 b = __ldg(reinterpret_cast<const float4*>(x0) + gw * 32 + lane);
    vs.x += b.x; vs.y += b.y; vs.z += b.z; vs.w += b.w;
    vq.x += b.x * b.x; vq.y += b.y * b.y; vq.z += b.z * b.z; vq.w += b.w * b.w;
    vmx.x = fmaxf(vmx.x, b.x); vmx.y = fmaxf(vmx.y, b.y);
    vmx.z = fmaxf(vmx.z, b.z); vmx.w = fmaxf(vmx.w, b.w);
    vmn.x = fminf(vmn.x, b.x); vmn.y = fminf(vmn.y, b.y);
    vmn.z = fminf(vmn.z, b.z); vmn.w = fminf(vmn.w, b.w);

    float dinv = 1.0f / ((float)(end - beg) + 1.0f);
    float4 mean = make_float4(vs.x * dinv, vs.y * dinv, vs.z * dinv, vs.w * dinv);
    float4 sqm  = make_float4(vq.x * dinv, vq.y * dinv, vq.z * dinv, vq.w * dinv);
    float4 stdv;
    stdv.x = sqrtf(fmaxf(sqm.x - mean.x * mean.x, 1e-6f));
    stdv.y = sqrtf(fmaxf(sqm.y - mean.y * mean.y, 1e-6f));
    stdv.z = sqrtf(fmaxf(sqm.z - mean.z * mean.z, 1e-6f));
    stdv.w = sqrtf(fmaxf(sqm.w - mean.w * mean.w, 1e-6f));

    float4* f = reinterpret_cast<float4*>(g_feats);
    f[(0 * N_NODES + gw) * 32 + lane] = mean;
    f[(1 * N_NODES + gw) * 32 + lane] = vmx;
    f[(2 * N_NODES + gw) * 32 + lane] = vmn;
    f[(3 * N_NODES + gw) * 32 + lane] = stdv;
}

// ---------------- tf32 tensor-core GEMM + LN + ReLU + residual --------------
__global__ void __launch_bounds__(256, 2)
k_gemm(const float* __restrict__ W, const float* __restrict__ bias,
       const float* __restrict__ lng, const float* __restrict__ lnb,
       const float* __restrict__ xin) {
    __shared__ float As[2][128 * ASTR];   // m-major, k permuted within 8-groups
    __shared__ float Bs[2][BK * BSTR];    // k-major [k][n]
    __shared__ float redS[128][4];
    __shared__ float redQ[128][4];

    int tid  = threadIdx.x;
    int lane = tid & 31, wid = tid >> 5;
    int wm = wid & 1, wn = wid >> 1;      // warp grid 2(m) x 4(n)
    int q = lane >> 2, p = lane & 3;
    int row0 = blockIdx.x * 128;

    int am = tid >> 1;
    int ak = (tid & 1) * 8;
    int grow = row0 + am;
    bool rok = grow < N_NODES;
    float sS = rok ? g_scaleS[grow] : 1.0f;
    float fac1 = sS, fac2 = 1.0f / fmaxf(sS, 1e-2f);
    int bk = tid >> 4, bn = (tid & 15) * 8;

    float acc[4][4][4];
#pragma unroll
    for (int i = 0; i < 4; i++)
#pragma unroll
        for (int j = 0; j < 4; j++)
#pragma unroll
            for (int c = 0; c < 4; c++) acc[i][j][c] = 0.0f;

    float ah[8];

    auto loadA = [&](int kt) {
        int kb   = kt * BK;
        int bblk = kb >> 7;               // 0..12, uniform
        int kc   = (kb & 127) + ak;
        if (rok) {
            const float* ptr;
            float fac;
            if (bblk < 12) {
                ptr = g_feats + ((bblk & 3) * N_NODES + grow) * 128 + kc;
                int jj = bblk >> 2;
                fac = (jj == 0) ? 1.0f : ((jj == 1) ? fac1 : fac2);
            } else {
                ptr = xin + grow * 128 + kc;
                fac = 1.0f;
            }
            float4 v0 = *reinterpret_cast<const float4*>(ptr);
            float4 v1 = *reinterpret_cast<const float4*>(ptr + 4);
            ah[0] = v0.x * fac; ah[1] = v0.y * fac; ah[2] = v0.z * fac; ah[3] = v0.w * fac;
            ah[4] = v1.x * fac; ah[5] = v1.y * fac; ah[6] = v1.z * fac; ah[7] = v1.w * fac;
        } else {
#pragma unroll
            for (int i = 0; i < 8; i++) ah[i] = 0.0f;
        }
    };

    auto stsA = [&](int buf) {
        float t[8];
#pragma unroll
        for (int i = 0; i < 8; i++) t[i] = f2tf(ah[i]);
        float* dst = &As[buf][am * ASTR + ak];
        *reinterpret_cast<float4*>(dst)     = make_float4(t[0], t[4], t[1], t[5]);
        *reinterpret_cast<float4*>(dst + 4) = make_float4(t[2], t[6], t[3], t[7]);
    };

    auto cpB = [&](int kt, int buf) {
        const float* wp = W + (kt * BK + bk) * 128 + bn;
        uint32_t d0 = (uint32_t)__cvta_generic_to_shared(&Bs[buf][bk * BSTR + bn]);
        asm volatile("cp.async.ca.shared.global [%0], [%1], 16;\n" :: "r"(d0), "l"(wp));
        asm volatile("cp.async.ca.shared.global [%0], [%1], 16;\n" :: "r"(d0 + 16), "l"(wp + 4));
    };

    loadA(0);
    cpB(0, 0);
    stsA(0);
    asm volatile("cp.async.commit_group;\n");
    asm volatile("cp.async.wait_group 0;\n");
    __syncthreads();

#pragma unroll 1
    for (int kt = 0; kt < NKT; kt++) {
        int buf = kt & 1;
        if (kt + 1 < NKT) {
            loadA(kt + 1);
            cpB(kt + 1, buf ^ 1);
            asm volatile("cp.async.commit_group;\n");
        }

#pragma unroll
        for (int h = 0; h < 2; h++) {
            int koff = h * 8;
            uint32_t a[4][4], b[4][2];
#pragma unroll
            for (int mt = 0; mt < 4; mt++) {
                int ra = wm * 64 + mt * 16 + q;
                float2 t0 = *reinterpret_cast<const float2*>(&As[buf][ra * ASTR + koff + 2 * p]);
                float2 t1 = *reinterpret_cast<const float2*>(&As[buf][(ra + 8) * ASTR + koff + 2 * p]);
                a[mt][0] = __float_as_uint(t0.x);
                a[mt][1] = __float_as_uint(t1.x);
                a[mt][2] = __float_as_uint(t0.y);
                a[mt][3] = __float_as_uint(t1.y);
            }
#pragma unroll
            for (int nt = 0; nt < 4; nt++) {
                int nc = wn * 32 + nt * 8 + q;
                b[nt][0] = __float_as_uint(Bs[buf][(koff + p) * BSTR + nc]);
                b[nt][1] = __float_as_uint(Bs[buf][(koff + p + 4) * BSTR + nc]);
            }
#pragma unroll
            for (int mt = 0; mt < 4; mt++)
#pragma unroll
                for (int nt = 0; nt < 4; nt++)
                    asm volatile(
                        "mma.sync.aligned.m16n8k8.row.col.f32.tf32.tf32.f32 "
                        "{%0,%1,%2,%3}, {%4,%5,%6,%7}, {%8,%9}, {%0,%1,%2,%3};"
                        : "+f"(acc[mt][nt][0]), "+f"(acc[mt][nt][1]),
                          "+f"(acc[mt][nt][2]), "+f"(acc[mt][nt][3])
                        : "r"(a[mt][0]), "r"(a[mt][1]), "r"(a[mt][2]), "r"(a[mt][3]),
                          "r"(b[nt][0]), "r"(b[nt][1]));
        }

        if (kt + 1 < NKT) {
            stsA(buf ^ 1);
            asm volatile("cp.async.wait_group 0;\n");
            __syncthreads();
        }
    }

    // ---- epilogue: bias + LN + ReLU + residual ----
    float2 bias2[4], lng2[4], lnb2[4];
#pragma unroll
    for (int nt = 0; nt < 4; nt++) {
        int c = wn * 32 + nt * 8 + 2 * p;
        bias2[nt] = *reinterpret_cast<const float2*>(bias + c);
        lng2[nt]  = *reinterpret_cast<const float2*>(lng + c);
        lnb2[nt]  = *reinterpret_cast<const float2*>(lnb + c);
    }

#pragma unroll
    for (int mt = 0; mt < 4; mt++) {
        float sA = 0.f, qA = 0.f, sB = 0.f, qB = 0.f;
#pragma unroll
        for (int nt = 0; nt < 4; nt++) {
            float v0 = acc[mt][nt][0] + bias2[nt].x;
            float v1 = acc[mt][nt][1] + bias2[nt].y;
            float v2 = acc[mt][nt][2] + bias2[nt].x;
            float v3 = acc[mt][nt][3] + bias2[nt].y;
            sA += v0 + v1; qA += v0 * v0 + v1 * v1;
            sB += v2 + v3; qB += v2 * v2 + v3 * v3;
        }
#pragma unroll
        for (int m = 1; m < 4; m <<= 1) {
            sA += __shfl_xor_sync(0xffffffffu, sA, m);
            qA += __shfl_xor_sync(0xffffffffu, qA, m);
            sB += __shfl_xor_sync(0xffffffffu, sB, m);
            qB += __shfl_xor_sync(0xffffffffu, qB, m);
        }
        if (p == 0) {
            int rA = wm * 64 + mt * 16 + q;
            redS[rA][wn] = sA; redQ[rA][wn] = qA;
            redS[rA + 8][wn] = sB; redQ[rA + 8][wn] = qB;
        }
    }
    __syncthreads();

#pragma unroll
    for (int mt = 0; mt < 4; mt++) {
#pragma unroll
        for (int half = 0; half < 2; half++) {
            int rloc = wm * 64 + mt * 16 + q + half * 8;
            int r = row0 + rloc;
            float s = redS[rloc][0] + redS[rloc][1] + redS[rloc][2] + redS[rloc][3];
            float sq = redQ[rloc][0] + redQ[rloc][1] + redQ[rloc][2] + redQ[rloc][3];
            float mu = s * (1.0f / 128.0f);
            float var = sq * (1.0f / 128.0f) - mu * mu;
            float rstd = rsqrtf(var + 1e-5f);
            if (r < N_NODES) {
#pragma unroll
                for (int nt = 0; nt < 4; nt++) {
                    int c = wn * 32 + nt * 8 + 2 * p;
                    float v0 = acc[mt][nt][half * 2 + 0] + bias2[nt].x;
                    float v1 = acc[mt][nt][half * 2 + 1] + bias2[nt].y;
                    float o0 = fmaxf((v0 - mu) * rstd * lng2[nt].x + lnb2[nt].x, 0.0f);
                    float o1 = fmaxf((v1 - mu) * rstd * lng2[nt].y + lnb2[nt].y, 0.0f);
                    float2 xr = *reinterpret_cast<const float2*>(xin + r * 128 + c);
                    *reinterpret_cast<float2*>(g_x + r * 128 + c) =
                        make_float2(o0 + xr.x, o1 + xr.y);
                }
            }
        }
    }
}

// ---------------- distmult scoring (warp per triple) ------------------------
__global__ void k_score(const int* __restrict__ src, const int* __restrict__ rel,
                        const int* __restrict__ dst, const float* __restrict__ qw,
                        float* __restrict__ out) {
    int gw   = (blockIdx.x * blockDim.x + threadIdx.x) >> 5;
    int lane = threadIdx.x & 31;
    if (gw >= 1024 * 32) return;
    int s = __ldg(src + gw), r = __ldg(rel + gw), d = __ldg(dst + gw);
    const float4* xv = reinterpret_cast<const float4*>(g_x);
    float4 a = __ldg(xv + s * 32 + lane);
    float4 qq = __ldg(reinterpret_cast<const float4*>(qw) + r * 32 + lane);
    float4 c = __ldg(xv + d * 32 + lane);
    float pr = a.x * qq.x * c.x + a.y * qq.y * c.y + a.z * qq.z * c.z + a.w * qq.w * c.w;
#pragma unroll
    for (int m = 16; m > 0; m >>= 1) pr += __shfl_xor_sync(0xffffffffu, pr, m);
    if (lane == 0) out[gw] = pr;
}

// ---------------- launcher ---------------------------------------------------
extern "C" void kernel_launch(void* const* d_in, const int* in_sizes, int n_in,
                              void* d_out, int out_size) {
    const float* x0    = (const float*)d_in[0];
    const int*   eidx  = (const int*)  d_in[1];
    const int*   etype = (const int*)  d_in[2];
    const float* ew    = (const float*)d_in[3];
    const float* relw  = (const float*)d_in[4];
    const float* linw  = (const float*)d_in[5];
    const float* linb  = (const float*)d_in[6];
    const float* lng   = (const float*)d_in[7];
    const float* lnb   = (const float*)d_in[8];
    const float* qw    = (const float*)d_in[9];
    const int*   src   = (const int*)  d_in[10];
    const int*   rel   = (const int*)  d_in[11];
    const int*   dst   = (const int*)  d_in[12];
    float*       out   = (float*)d_out;

    const int* esrc = eidx;
    const int* edst = eidx + N_EDGES;

    float* gx;   cudaGetSymbolAddress((void**)&gx, g_x);
    float* gW;   cudaGetSymbolAddress((void**)&gW, g_W);
    int*   gdeg; cudaGetSymbolAddress((void**)&gdeg, g_deg);

    cudaMemsetAsync(gdeg, 0, N_NODES * sizeof(int));

    // launch order chosen so launch #3 (0-based) is the first k_agg (ncu capture slot)
    k_hist<<<(N_EDGES + 255) / 256, 256>>>(edst);                       // 0
    k_scan<<<1, 1024>>>();                                              // 1
    k_fill<<<(N_EDGES + 255) / 256, 256>>>(esrc, edst, etype, ew);      // 2

    for (int l = 0; l < 4; l++) {
        const float* xin = (l == 0) ? x0 : gx;
        k_agg<<<(N_NODES * 32 + 255) / 256, 256>>>(xin, x0, relw + l * N_REL * DIM);
        if (l == 0)
            k_cvtW<<<(4 * KDIM * DIM + 255) / 256, 256>>>(linw);
        k_gemm<<<(N_NODES + 127) / 128, 256>>>(gW + l * KDIM * DIM,
                                               linb + l * DIM,
                                               lng + l * DIM,
                                               lnb + l * DIM,
                                               xin);
    }

    k_score<<<(1024 * 32 * 32 + 255) / 256, 256>>>(src, rel, dst, qw, out);
}

// round 9
// speedup vs baseline: 1.2880x; 1.2880x over previous
#include <cuda_runtime.h>
#include <cuda_fp16.h>
#include <stdint.h>
#include <math.h>

#define N_NODES 50000
#define N_EDGES 500000
#define DIM     128
#define N_REL   51
#define KDIM    1664   // 13*128
#define BK      32
#define NKT     (KDIM / BK)   // 52
#define ASTRH   40     // halves per A row (80B)
#define BSTRH   40     // halves per B row (80B)
#define NGRP    6250   // N_NODES / 8

// ---------------- scratch (device globals; no allocation allowed) ----------
__device__ int   g_deg[N_NODES];
__device__ int   g_off[N_NODES + 1];
__device__ int   g_fill[N_NODES];
__device__ int   g_esrc[N_EDGES];
__device__ int   g_etype[N_EDGES];
__device__ float g_ew[N_EDGES];
__device__ float g_scaleS[N_NODES];
__device__ float g_x[N_NODES * DIM];
__device__ float g_feats[4 * N_NODES * DIM];   // [feat(4)][node][dim]
__device__ __half g_Wth[4 * DIM * KDIM];       // transposed half weights [l][n][k]

// ---------------- preprocessing kernels ------------------------------------
// transpose + round weights to half: g_Wth[l][n][k] = h(linw[l][k][n])
__global__ void k_cvtWth(const float* __restrict__ linw) {
    __shared__ float tile[32][33];
    int l = blockIdx.z;
    int k0 = blockIdx.x * 32, n0 = blockIdx.y * 32;
    const float* src = linw + l * KDIM * DIM;
#pragma unroll
    for (int r = 0; r < 4; r++) {
        int k = k0 + threadIdx.y + r * 8;
        tile[threadIdx.y + r * 8][threadIdx.x] = src[k * DIM + n0 + threadIdx.x];
    }
    __syncthreads();
    __half* dst = g_Wth + l * DIM * KDIM;
#pragma unroll
    for (int r = 0; r < 4; r++) {
        int n = n0 + threadIdx.y + r * 8;
        dst[n * KDIM + k0 + threadIdx.x] =
            __float2half_rn(tile[threadIdx.x][threadIdx.y + r * 8]);
    }
}

__global__ void k_hist(const int* __restrict__ edst) {
    int e = blockIdx.x * blockDim.x + threadIdx.x;
    if (e < N_EDGES) atomicAdd(&g_deg[edst[e]], 1);
}

// single block, 1024 threads; 8 elements per thread per chunk.
__global__ void k_scan() {
    __shared__ int   wsum[32];
    __shared__ int   carry_sh;
    __shared__ float fred[32];
    __shared__ float ssum_sh;
    int tid  = threadIdx.x;
    int lane = tid & 31, wid = tid >> 5;
    if (tid == 0) carry_sh = 0;
    __syncthreads();

    float ls = 0.0f;
#pragma unroll 1
    for (int c = 0; c < 7; c++) {
        int g = c * 1024 + tid;
        int v[8];
        int tsum = 0;
        if (g < NGRP) {
            int4 a = *reinterpret_cast<const int4*>(g_deg + g * 8);
            int4 b = *reinterpret_cast<const int4*>(g_deg + g * 8 + 4);
            v[0] = a.x; v[1] = a.y; v[2] = a.z; v[3] = a.w;
            v[4] = b.x; v[5] = b.y; v[6] = b.z; v[7] = b.w;
#pragma unroll
            for (int j = 0; j < 8; j++) tsum += v[j];
        } else {
#pragma unroll
            for (int j = 0; j < 8; j++) v[j] = 0;
        }
        int x = tsum;
#pragma unroll
        for (int off = 1; off < 32; off <<= 1) {
            int y = __shfl_up_sync(0xffffffffu, x, off);
            if (lane >= off) x += y;
        }
        if (lane == 31) wsum[wid] = x;
        __syncthreads();
        if (wid == 0) {
            int w = wsum[lane];
#pragma unroll
            for (int off = 1; off < 32; off <<= 1) {
                int y = __shfl_up_sync(0xffffffffu, w, off);
                if (lane >= off) w += y;
            }
            wsum[lane] = w;
        }
        __syncthreads();
        int wpre = (wid > 0) ? wsum[wid - 1] : 0;
        int excl = carry_sh + wpre + x - tsum;
        if (g < NGRP) {
            int run = excl;
#pragma unroll
            for (int j = 0; j < 8; j++) {
                g_off[g * 8 + j]  = run;
                g_fill[g * 8 + j] = run;
                run += v[j];
                ls += logf((float)v[j] + 1.0f);
            }
        }
        __syncthreads();
        if (tid == 1023) carry_sh += wsum[31];
        __syncthreads();
    }
    if (tid == 0) g_off[N_NODES] = N_EDGES;

#pragma unroll
    for (int m = 16; m > 0; m >>= 1) ls += __shfl_xor_sync(0xffffffffu, ls, m);
    if (lane == 0) fred[wid] = ls;
    __syncthreads();
    if (wid == 0) {
        float s = fred[lane];
#pragma unroll
        for (int m = 16; m > 0; m >>= 1) s += __shfl_xor_sync(0xffffffffu, s, m);
        if (lane == 0) ssum_sh = s;
    }
    __syncthreads();
    float inv_mean = (float)N_NODES / ssum_sh;
#pragma unroll 1
    for (int g = tid; g < NGRP; g += 1024) {
        int4 a = *reinterpret_cast<const int4*>(g_deg + g * 8);
        int4 b = *reinterpret_cast<const int4*>(g_deg + g * 8 + 4);
        float4 o0, o1;
        o0.x = logf((float)a.x + 1.0f) * inv_mean;
        o0.y = logf((float)a.y + 1.0f) * inv_mean;
        o0.z = logf((float)a.z + 1.0f) * inv_mean;
        o0.w = logf((float)a.w + 1.0f) * inv_mean;
        o1.x = logf((float)b.x + 1.0f) * inv_mean;
        o1.y = logf((float)b.y + 1.0f) * inv_mean;
        o1.z = logf((float)b.z + 1.0f) * inv_mean;
        o1.w = logf((float)b.w + 1.0f) * inv_mean;
        *reinterpret_cast<float4*>(g_scaleS + g * 8)     = o0;
        *reinterpret_cast<float4*>(g_scaleS + g * 8 + 4) = o1;
    }
}

__global__ void k_fill(const int* __restrict__ esrc, const int* __restrict__ edst,
                       const int* __restrict__ etype, const float* __restrict__ ew) {
    int e = blockIdx.x * blockDim.x + threadIdx.x;
    if (e >= N_EDGES) return;
    int d = edst[e];
    int p = atomicAdd(&g_fill[d], 1);
    g_esrc[p]  = esrc[e];
    g_etype[p] = etype[e];
    g_ew[p]    = ew[e];
}

// ---------------- per-layer aggregation (warp per node) --------------------
__global__ void k_agg(const float* __restrict__ xin, const float* __restrict__ x0,
                      const float* __restrict__ relw) {
    int gw   = (blockIdx.x * blockDim.x + threadIdx.x) >> 5;
    int lane = threadIdx.x & 31;
    if (gw >= N_NODES) return;
    int beg = g_off[gw], end = g_off[gw + 1];

    float4 vs  = make_float4(0.f, 0.f, 0.f, 0.f);
    float4 vq  = make_float4(0.f, 0.f, 0.f, 0.f);
    float4 vmx = make_float4(-INFINITY, -INFINITY, -INFINITY, -INFINITY);
    float4 vmn = make_float4( INFINITY,  INFINITY,  INFINITY,  INFINITY);

    const float4* xv = reinterpret_cast<const float4*>(xin);
    const float4* rv = reinterpret_cast<const float4*>(relw);

    for (int e = beg; e < end; e++) {
        int   s = __ldg(g_esrc + e);
        int   t = __ldg(g_etype + e);
        float w = __ldg(g_ew + e);
        float4 a = __ldg(xv + s * 32 + lane);
        float4 r = __ldg(rv + t * 32 + lane);
        float mx = a.x * r.x * w, my = a.y * r.y * w, mz = a.z * r.z * w, mw = a.w * r.w * w;
        vs.x += mx; vs.y += my; vs.z += mz; vs.w += mw;
        vq.x += mx * mx; vq.y += my * my; vq.z += mz * mz; vq.w += mw * mw;
        vmx.x = fmaxf(vmx.x, mx); vmx.y = fmaxf(vmx.y, my);
        vmx.z = fmaxf(vmx.z, mz); vmx.w = fmaxf(vmx.w, mw);
        vmn.x = fminf(vmn.x, mx); vmn.y = fminf(vmn.y, my);
        vmn.z = fminf(vmn.z, mz); vmn.w = fminf(vmn.w, mw);
    }

    float4 b = __ldg(reinterpret_cast<const float4*>(x0) + gw * 32 + lane);
    vs.x += b.x; vs.y += b.y; vs.z += b.z; vs.w += b.w;
    vq.x += b.x * b.x; vq.y += b.y * b.y; vq.z += b.z * b.z; vq.w += b.w * b.w;
    vmx.x = fmaxf(vmx.x, b.x); vmx.y = fmaxf(vmx.y, b.y);
    vmx.z = fmaxf(vmx.z, b.z); vmx.w = fmaxf(vmx.w, b.w);
    vmn.x = fminf(vmn.x, b.x); vmn.y = fminf(vmn.y, b.y);
    vmn.z = fminf(vmn.z, b.z); vmn.w = fminf(vmn.w, b.w);

    float dinv = 1.0f / ((float)(end - beg) + 1.0f);
    float4 mean = make_float4(vs.x * dinv, vs.y * dinv, vs.z * dinv, vs.w * dinv);
    float4 sqm  = make_float4(vq.x * dinv, vq.y * dinv, vq.z * dinv, vq.w * dinv);
    float4 stdv;
    stdv.x = sqrtf(fmaxf(sqm.x - mean.x * mean.x, 1e-6f));
    stdv.y = sqrtf(fmaxf(sqm.y - mean.y * mean.y, 1e-6f));
    stdv.z = sqrtf(fmaxf(sqm.z - mean.z * mean.z, 1e-6f));
    stdv.w = sqrtf(fmaxf(sqm.w - mean.w * mean.w, 1e-6f));

    float4* f = reinterpret_cast<float4*>(g_feats);
    f[(0 * N_NODES + gw) * 32 + lane] = mean;
    f[(1 * N_NODES + gw) * 32 + lane] = vmx;
    f[(2 * N_NODES + gw) * 32 + lane] = vmn;
    f[(3 * N_NODES + gw) * 32 + lane] = stdv;
}

// ---------------- fp16 tensor-core GEMM + LN + ReLU + residual --------------
// C[50000,128] = A[50000,1664] @ W[1664,128]; A built on the fly (half).
// 128x128 block tile, 8 warps (2x4), warp tile 64x32, mma.m16n8k16.f16,
// fragments via ldmatrix, fp32 accumulate.
__global__ void __launch_bounds__(256, 2)
k_gemm(const __half* __restrict__ Wt, const float* __restrict__ bias,
       const float* __restrict__ lng, const float* __restrict__ lnb,
       const float* __restrict__ xin) {
    __shared__ __align__(16) __half As[2][128 * ASTRH];  // [m][k] halves
    __shared__ __align__(16) __half Bs[2][128 * BSTRH];  // [n][k] halves
    __shared__ float redS[128][4];
    __shared__ float redQ[128][4];

    int tid  = threadIdx.x;
    int lane = tid & 31, wid = tid >> 5;
    int wm = wid & 1, wn = wid >> 1;      // warp grid 2(m) x 4(n)
    int q = lane >> 2, p = lane & 3;
    int lrow = lane & 7;
    int lb3  = (lane >> 3) & 1;
    int lb4  = (lane >> 4) & 1;
    int row0 = blockIdx.x * 128;

    // A loader: thread -> (row am, k-half of 16 halves)
    int am = tid >> 1;
    int akh = tid & 1;
    int grow = row0 + am;
    bool rok = grow < N_NODES;
    float sS = rok ? g_scaleS[grow] : 1.0f;
    float facs[3] = {1.0f, sS, 1.0f / fmaxf(sS, 1e-2f)};
    // B loader: thread -> (row n, half of row)
    int bn = tid >> 1, bh = tid & 1;

    float acc[4][4][4];
#pragma unroll
    for (int i = 0; i < 4; i++)
#pragma unroll
        for (int j = 0; j < 4; j++)
#pragma unroll
            for (int c = 0; c < 4; c++) acc[i][j][c] = 0.0f;

    float rv[16];
#pragma unroll
    for (int i = 0; i < 16; i++) rv[i] = 0.0f;
    float curfac = 1.0f;

    auto loadA = [&](int kt) {
        int bblk = kt >> 2;                        // 0..12, uniform
        int kc   = (kt & 3) * 32 + akh * 16;
        if (rok) {
            const float* ptr;
            if (bblk < 12) {
                ptr = g_feats + ((bblk & 3) * N_NODES + grow) * 128 + kc;
                int jj = bblk >> 2;
                curfac = facs[jj];
            } else {
                ptr = xin + grow * 128 + kc;
                curfac = 1.0f;
            }
#pragma unroll
            for (int g = 0; g < 4; g++) {
                float4 v = *reinterpret_cast<const float4*>(ptr + g * 4);
                rv[g * 4 + 0] = v.x; rv[g * 4 + 1] = v.y;
                rv[g * 4 + 2] = v.z; rv[g * 4 + 3] = v.w;
            }
        }
    };

    auto stsA = [&](int buf) {
        uint32_t h[8];
#pragma unroll
        for (int g = 0; g < 8; g++) {
            __half2 t = __floats2half2_rn(rv[g * 2] * curfac, rv[g * 2 + 1] * curfac);
            h[g] = *reinterpret_cast<uint32_t*>(&t);
        }
        char* dst = reinterpret_cast<char*>(&As[buf][0]) + am * 80 + akh * 32;
#pragma unroll
        for (int g = 0; g < 4; g++)
            *reinterpret_cast<uint2*>(dst + g * 8) = make_uint2(h[g * 2], h[g * 2 + 1]);
    };

    auto cpB = [&](int kt, int buf) {
        const __half* src = Wt + bn * KDIM + kt * BK + bh * 16;
        uint32_t d0 = (uint32_t)__cvta_generic_to_shared(
            reinterpret_cast<char*>(&Bs[buf][0]) + bn * 80 + bh * 32);
        asm volatile("cp.async.ca.shared.global [%0], [%1], 16;\n" :: "r"(d0), "l"(src));
        asm volatile("cp.async.ca.shared.global [%0], [%1], 16;\n"
                     :: "r"(d0 + 16), "l"(src + 8));
    };

    loadA(0);
    cpB(0, 0);
    stsA(0);
    asm volatile("cp.async.commit_group;\n");
    asm volatile("cp.async.wait_group 0;\n");
    __syncthreads();

#pragma unroll 1
    for (int kt = 0; kt < NKT; kt++) {
        int buf = kt & 1;
        if (kt + 1 < NKT) {
            loadA(kt + 1);
            cpB(kt + 1, buf ^ 1);
            asm volatile("cp.async.commit_group;\n");
        }

#pragma unroll
        for (int kk = 0; kk < 2; kk++) {
            uint32_t a[4][4], b[2][4];
            // A fragments: 4x ldmatrix.x4
#pragma unroll
            for (int mt = 0; mt < 4; mt++) {
                int ar = wm * 64 + mt * 16 + lrow + lb3 * 8;
                int ac = kk * 16 + lb4 * 8;
                uint32_t addr = (uint32_t)__cvta_generic_to_shared(
                    reinterpret_cast<char*>(&As[buf][0]) + ar * 80 + ac * 2);
                asm volatile(
                    "ldmatrix.sync.aligned.m8n8.x4.shared.b16 {%0,%1,%2,%3}, [%4];"
                    : "=r"(a[mt][0]), "=r"(a[mt][1]), "=r"(a[mt][2]), "=r"(a[mt][3])
                    : "r"(addr));
            }
            // B fragments: 2x ldmatrix.x4 (each covers two n-tiles of 8)
#pragma unroll
            for (int ntp = 0; ntp < 2; ntp++) {
                int br = wn * 32 + ntp * 16 + lrow + lb4 * 8;
                int bc = kk * 16 + lb3 * 8;
                uint32_t addr = (uint32_t)__cvta_generic_to_shared(
                    reinterpret_cast<char*>(&Bs[buf][0]) + br * 80 + bc * 2);
                asm volatile(
                    "ldmatrix.sync.aligned.m8n8.x4.shared.b16 {%0,%1,%2,%3}, [%4];"
                    : "=r"(b[ntp][0]), "=r"(b[ntp][1]), "=r"(b[ntp][2]), "=r"(b[ntp][3])
                    : "r"(addr));
            }
#pragma unroll
            for (int mt = 0; mt < 4; mt++)
#pragma unroll
                for (int nt = 0; nt < 4; nt++) {
                    int ntp = nt >> 1, hh = (nt & 1) * 2;
                    asm volatile(
                        "mma.sync.aligned.m16n8k16.row.col.f32.f16.f16.f32 "
                        "{%0,%1,%2,%3}, {%4,%5,%6,%7}, {%8,%9}, {%0,%1,%2,%3};"
                        : "+f"(acc[mt][nt][0]), "+f"(acc[mt][nt][1]),
                          "+f"(acc[mt][nt][2]), "+f"(acc[mt][nt][3])
                        : "r"(a[mt][0]), "r"(a[mt][1]), "r"(a[mt][2]), "r"(a[mt][3]),
                          "r"(b[ntp][hh]), "r"(b[ntp][hh + 1]));
                }
        }

        if (kt + 1 < NKT) {
            stsA(buf ^ 1);
            asm volatile("cp.async.wait_group 0;\n");
            __syncthreads();
        }
    }

    // ---- epilogue: bias + LN + ReLU + residual ----
    float2 bias2[4], lng2[4], lnb2[4];
#pragma unroll
    for (int nt = 0; nt < 4; nt++) {
        int c = wn * 32 + nt * 8 + 2 * p;
        bias2[nt] = *reinterpret_cast<const float2*>(bias + c);
        lng2[nt]  = *reinterpret_cast<const float2*>(lng + c);
        lnb2[nt]  = *reinterpret_cast<const float2*>(lnb + c);
    }

#pragma unroll
    for (int mt = 0; mt < 4; mt++) {
        float sA = 0.f, qA = 0.f, sB = 0.f, qB = 0.f;
#pragma unroll
        for (int nt = 0; nt < 4; nt++) {
            float v0 = acc[mt][nt][0] + bias2[nt].x;
            float v1 = acc[mt][nt][1] + bias2[nt].y;
            float v2 = acc[mt][nt][2] + bias2[nt].x;
            float v3 = acc[mt][nt][3] + bias2[nt].y;
            sA += v0 + v1; qA += v0 * v0 + v1 * v1;
            sB += v2 + v3; qB += v2 * v2 + v3 * v3;
        }
#pragma unroll
        for (int m = 1; m < 4; m <<= 1) {
            sA += __shfl_xor_sync(0xffffffffu, sA, m);
            qA += __shfl_xor_sync(0xffffffffu, qA, m);
            sB += __shfl_xor_sync(0xffffffffu, sB, m);
            qB += __shfl_xor_sync(0xffffffffu, qB, m);
        }
        if (p == 0) {
            int rA = wm * 64 + mt * 16 + q;
            redS[rA][wn] = sA; redQ[rA][wn] = qA;
            redS[rA + 8][wn] = sB; redQ[rA + 8][wn] = qB;
        }
    }
    __syncthreads();

#pragma unroll
    for (int mt = 0; mt < 4; mt++) {
#pragma unroll
        for (int half = 0; half < 2; half++) {
            int rloc = wm * 64 + mt * 16 + q + half * 8;
            int r = row0 + rloc;
            float s = redS[rloc][0] + redS[rloc][1] + redS[rloc][2] + redS[rloc][3];
            float sq = redQ[rloc][0] + redQ[rloc][1] + redQ[rloc][2] + redQ[rloc][3];
            float mu = s * (1.0f / 128.0f);
            float var = sq * (1.0f / 128.0f) - mu * mu;
            float rstd = rsqrtf(var + 1e-5f);
            if (r < N_NODES) {
#pragma unroll
                for (int nt = 0; nt < 4; nt++) {
                    int c = wn * 32 + nt * 8 + 2 * p;
                    float v0 = acc[mt][nt][half * 2 + 0] + bias2[nt].x;
                    float v1 = acc[mt][nt][half * 2 + 1] + bias2[nt].y;
                    float o0 = fmaxf((v0 - mu) * rstd * lng2[nt].x + lnb2[nt].x, 0.0f);
                    float o1 = fmaxf((v1 - mu) * rstd * lng2[nt].y + lnb2[nt].y, 0.0f);
                    float2 xr = *reinterpret_cast<const float2*>(xin + r * 128 + c);
                    *reinterpret_cast<float2*>(g_x + r * 128 + c) =
                        make_float2(o0 + xr.x, o1 + xr.y);
                }
            }
        }
    }
}

// ---------------- distmult scoring (warp per triple) ------------------------
__global__ void k_score(const int* __restrict__ src, const int* __restrict__ rel,
                        const int* __restrict__ dst, const float* __restrict__ qw,
                        float* __restrict__ out) {
    int gw   = (blockIdx.x * blockDim.x + threadIdx.x) >> 5;
    int lane = threadIdx.x & 31;
    if (gw >= 1024 * 32) return;
    int s = __ldg(src + gw), r = __ldg(rel + gw), d = __ldg(dst + gw);
    const float4* xv = reinterpret_cast<const float4*>(g_x);
    float4 a = __ldg(xv + s * 32 + lane);
    float4 qq = __ldg(reinterpret_cast<const float4*>(qw) + r * 32 + lane);
    float4 c = __ldg(xv + d * 32 + lane);
    float pr = a.x * qq.x * c.x + a.y * qq.y * c.y + a.z * qq.z * c.z + a.w * qq.w * c.w;
#pragma unroll
    for (int m = 16; m > 0; m >>= 1) pr += __shfl_xor_sync(0xffffffffu, pr, m);
    if (lane == 0) out[gw] = pr;
}

// ---------------- launcher ---------------------------------------------------
extern "C" void kernel_launch(void* const* d_in, const int* in_sizes, int n_in,
                              void* d_out, int out_size) {
    const float* x0    = (const float*)d_in[0];
    const int*   eidx  = (const int*)  d_in[1];
    const int*   etype = (const int*)  d_in[2];
    const float* ew    = (const float*)d_in[3];
    const float* relw  = (const float*)d_in[4];
    const float* linw  = (const float*)d_in[5];
    const float* linb  = (const float*)d_in[6];
    const float* lng   = (const float*)d_in[7];
    const float* lnb   = (const float*)d_in[8];
    const float* qw    = (const float*)d_in[9];
    const int*   src   = (const int*)  d_in[10];
    const int*   rel   = (const int*)  d_in[11];
    const int*   dst   = (const int*)  d_in[12];
    float*       out   = (float*)d_out;

    const int* esrc = eidx;
    const int* edst = eidx + N_EDGES;

    float*  gx;   cudaGetSymbolAddress((void**)&gx, g_x);
    __half* gWh;  cudaGetSymbolAddress((void**)&gWh, g_Wth);
    int*    gdeg; cudaGetSymbolAddress((void**)&gdeg, g_deg);

    cudaMemsetAsync(gdeg, 0, N_NODES * sizeof(int));

    k_hist<<<(N_EDGES + 255) / 256, 256>>>(edst);
    k_scan<<<1, 1024>>>();
    k_fill<<<(N_EDGES + 255) / 256, 256>>>(esrc, edst, etype, ew);

    for (int l = 0; l < 4; l++) {
        const float* xin = (l == 0) ? x0 : gx;
        k_agg<<<(N_NODES * 32 + 255) / 256, 256>>>(xin, x0, relw + l * N_REL * DIM);
        if (l == 0)
            k_cvtWth<<<dim3(KDIM / 32, DIM / 32, 4), dim3(32, 8)>>>(linw);
        k_gemm<<<(N_NODES + 127) / 128, 256>>>(gWh + (size_t)l * DIM * KDIM,
                                               linb + l * DIM,
                                               lng + l * DIM,
                                               lnb + l * DIM,
                                               xin);
    }

    k_score<<<(1024 * 32 * 32 + 255) / 256, 256>>>(src, rel, dst, qw, out);
}

// round 10
// speedup vs baseline: 1.6518x; 1.2824x over previous
#include <cuda_runtime.h>
#include <cuda_fp16.h>
#include <stdint.h>
#include <math.h>

#define N_NODES 50000
#define N_EDGES 500000
#define DIM     128
#define N_REL   51
#define KDIM    1664   // 13*128
#define BK      32
#define NKT     (KDIM / BK)   // 52
#define NSTG    4
#define TILEB   10240          // bytes per operand per stage (128 rows * 80B)
#define NGRP    6250           // N_NODES / 8

// ---------------- scratch (device globals; no allocation allowed) ----------
__device__ int    g_deg[N_NODES];
__device__ int    g_off[N_NODES + 1];
__device__ int    g_fill[N_NODES];
__device__ int    g_esrc[N_EDGES];
__device__ int    g_etype[N_EDGES];
__device__ float  g_ew[N_EDGES];
__device__ float  g_scaleS[N_NODES];
__device__ float  g_x[N_NODES * DIM];
__device__ __half g_Ah[(size_t)NKT * N_NODES * 32];  // chunk-major half A matrix
__device__ __half g_Wth[4 * DIM * KDIM];             // transposed half weights [l][n][k]

// ---------------- preprocessing kernels ------------------------------------
// transpose + round weights to half: g_Wth[l][n][k] = h(linw[l][k][n])
__global__ void k_cvtWth(const float* __restrict__ linw) {
    __shared__ float tile[32][33];
    int l = blockIdx.z;
    int k0 = blockIdx.x * 32, n0 = blockIdx.y * 32;
    const float* src = linw + l * KDIM * DIM;
#pragma unroll
    for (int r = 0; r < 4; r++) {
        int k = k0 + threadIdx.y + r * 8;
        tile[threadIdx.y + r * 8][threadIdx.x] = src[k * DIM + n0 + threadIdx.x];
    }
    __syncthreads();
    __half* dst = g_Wth + l * DIM * KDIM;
#pragma unroll
    for (int r = 0; r < 4; r++) {
        int n = n0 + threadIdx.y + r * 8;
        dst[n * KDIM + k0 + threadIdx.x] =
            __float2half_rn(tile[threadIdx.x][threadIdx.y + r * 8]);
    }
}

// convert x (fp32 row-major) into A chunks 48..51 (half)
__global__ void k_cvtx(const float* __restrict__ x) {
    int i = blockIdx.x * blockDim.x + threadIdx.x;   // over N*32 groups of 4 cols
    if (i >= N_NODES * 32) return;
    int n = i >> 5, g = i & 31;
    int col = g * 4;
    float4 v = __ldg(reinterpret_cast<const float4*>(x + n * 128) + g);
    int ch = 48 + (col >> 5);
    int off = col & 31;
    __half2 lo = __floats2half2_rn(v.x, v.y);
    __half2 hi = __floats2half2_rn(v.z, v.w);
    *reinterpret_cast<uint2*>(g_Ah + ((size_t)ch * N_NODES + n) * 32 + off) =
        make_uint2(*reinterpret_cast<uint32_t*>(&lo), *reinterpret_cast<uint32_t*>(&hi));
}

__global__ void k_hist(const int* __restrict__ edst) {
    int e = blockIdx.x * blockDim.x + threadIdx.x;
    if (e < N_EDGES) atomicAdd(&g_deg[edst[e]], 1);
}

// single block, 1024 threads; 8 elements per thread per chunk.
__global__ void k_scan() {
    __shared__ int   wsum[32];
    __shared__ int   carry_sh;
    __shared__ float fred[32];
    __shared__ float ssum_sh;
    int tid  = threadIdx.x;
    int lane = tid & 31, wid = tid >> 5;
    if (tid == 0) carry_sh = 0;
    __syncthreads();

    float ls = 0.0f;
#pragma unroll 1
    for (int c = 0; c < 7; c++) {
        int g = c * 1024 + tid;
        int v[8];
        int tsum = 0;
        if (g < NGRP) {
            int4 a = *reinterpret_cast<const int4*>(g_deg + g * 8);
            int4 b = *reinterpret_cast<const int4*>(g_deg + g * 8 + 4);
            v[0] = a.x; v[1] = a.y; v[2] = a.z; v[3] = a.w;
            v[4] = b.x; v[5] = b.y; v[6] = b.z; v[7] = b.w;
#pragma unroll
            for (int j = 0; j < 8; j++) tsum += v[j];
        } else {
#pragma unroll
            for (int j = 0; j < 8; j++) v[j] = 0;
        }
        int x = tsum;
#pragma unroll
        for (int off = 1; off < 32; off <<= 1) {
            int y = __shfl_up_sync(0xffffffffu, x, off);
            if (lane >= off) x += y;
        }
        if (lane == 31) wsum[wid] = x;
        __syncthreads();
        if (wid == 0) {
            int w = wsum[lane];
#pragma unroll
            for (int off = 1; off < 32; off <<= 1) {
                int y = __shfl_up_sync(0xffffffffu, w, off);
                if (lane >= off) w += y;
            }
            wsum[lane] = w;
        }
        __syncthreads();
        int wpre = (wid > 0) ? wsum[wid - 1] : 0;
        int excl = carry_sh + wpre + x - tsum;
        if (g < NGRP) {
            int run = excl;
#pragma unroll
            for (int j = 0; j < 8; j++) {
                g_off[g * 8 + j]  = run;
                g_fill[g * 8 + j] = run;
                run += v[j];
                ls += logf((float)v[j] + 1.0f);
            }
        }
        __syncthreads();
        if (tid == 1023) carry_sh += wsum[31];
        __syncthreads();
    }
    if (tid == 0) g_off[N_NODES] = N_EDGES;

#pragma unroll
    for (int m = 16; m > 0; m >>= 1) ls += __shfl_xor_sync(0xffffffffu, ls, m);
    if (lane == 0) fred[wid] = ls;
    __syncthreads();
    if (wid == 0) {
        float s = fred[lane];
#pragma unroll
        for (int m = 16; m > 0; m >>= 1) s += __shfl_xor_sync(0xffffffffu, s, m);
        if (lane == 0) ssum_sh = s;
    }
    __syncthreads();
    float inv_mean = (float)N_NODES / ssum_sh;
#pragma unroll 1
    for (int g = tid; g < NGRP; g += 1024) {
        int4 a = *reinterpret_cast<const int4*>(g_deg + g * 8);
        int4 b = *reinterpret_cast<const int4*>(g_deg + g * 8 + 4);
        float4 o0, o1;
        o0.x = logf((float)a.x + 1.0f) * inv_mean;
        o0.y = logf((float)a.y + 1.0f) * inv_mean;
        o0.z = logf((float)a.z + 1.0f) * inv_mean;
        o0.w = logf((float)a.w + 1.0f) * inv_mean;
        o1.x = logf((float)b.x + 1.0f) * inv_mean;
        o1.y = logf((float)b.y + 1.0f) * inv_mean;
        o1.z = logf((float)b.z + 1.0f) * inv_mean;
        o1.w = logf((float)b.w + 1.0f) * inv_mean;
        *reinterpret_cast<float4*>(g_scaleS + g * 8)     = o0;
        *reinterpret_cast<float4*>(g_scaleS + g * 8 + 4) = o1;
    }
}

__global__ void k_fill(const int* __restrict__ esrc, const int* __restrict__ edst,
                       const int* __restrict__ etype, const float* __restrict__ ew) {
    int e = blockIdx.x * blockDim.x + threadIdx.x;
    if (e >= N_EDGES) return;
    int d = edst[e];
    int p = atomicAdd(&g_fill[d], 1);
    g_esrc[p]  = esrc[e];
    g_etype[p] = etype[e];
    g_ew[p]    = ew[e];
}

// ---------------- per-layer aggregation (warp per node) --------------------
// writes the 12 scale*feat blocks directly as half into g_Ah (chunk-major)
__global__ void k_agg(const float* __restrict__ xin, const float* __restrict__ x0,
                      const float* __restrict__ relw) {
    int gw   = (blockIdx.x * blockDim.x + threadIdx.x) >> 5;
    int lane = threadIdx.x & 31;
    if (gw >= N_NODES) return;
    int beg = g_off[gw], end = g_off[gw + 1];

    float4 vs  = make_float4(0.f, 0.f, 0.f, 0.f);
    float4 vq  = make_float4(0.f, 0.f, 0.f, 0.f);
    float4 vmx = make_float4(-INFINITY, -INFINITY, -INFINITY, -INFINITY);
    float4 vmn = make_float4( INFINITY,  INFINITY,  INFINITY,  INFINITY);

    const float4* xv = reinterpret_cast<const float4*>(xin);
    const float4* rv = reinterpret_cast<const float4*>(relw);

    for (int e = beg; e < end; e++) {
        int   s = __ldg(g_esrc + e);
        int   t = __ldg(g_etype + e);
        float w = __ldg(g_ew + e);
        float4 a = __ldg(xv + s * 32 + lane);
        float4 r = __ldg(rv + t * 32 + lane);
        float mx = a.x * r.x * w, my = a.y * r.y * w, mz = a.z * r.z * w, mw = a.w * r.w * w;
        vs.x += mx; vs.y += my; vs.z += mz; vs.w += mw;
        vq.x += mx * mx; vq.y += my * my; vq.z += mz * mz; vq.w += mw * mw;
        vmx.x = fmaxf(vmx.x, mx); vmx.y = fmaxf(vmx.y, my);
        vmx.z = fmaxf(vmx.z, mz); vmx.w = fmaxf(vmx.w, mw);
        vmn.x = fminf(vmn.x, mx); vmn.y = fminf(vmn.y, my);
        vmn.z = fminf(vmn.z, mz); vmn.w = fminf(vmn.w, mw);
    }

    float4 b = __ldg(reinterpret_cast<const float4*>(x0) + gw * 32 + lane);
    vs.x += b.x; vs.y += b.y; vs.z += b.z; vs.w += b.w;
    vq.x += b.x * b.x; vq.y += b.y * b.y; vq.z += b.z * b.z; vq.w += b.w * b.w;
    vmx.x = fmaxf(vmx.x, b.x); vmx.y = fmaxf(vmx.y, b.y);
    vmx.z = fmaxf(vmx.z, b.z); vmx.w = fmaxf(vmx.w, b.w);
    vmn.x = fminf(vmn.x, b.x); vmn.y = fminf(vmn.y, b.y);
    vmn.z = fminf(vmn.z, b.z); vmn.w = fminf(vmn.w, b.w);

    float dinv = 1.0f / ((float)(end - beg) + 1.0f);
    float4 mean = make_float4(vs.x * dinv, vs.y * dinv, vs.z * dinv, vs.w * dinv);
    float4 sqm  = make_float4(vq.x * dinv, vq.y * dinv, vq.z * dinv, vq.w * dinv);
    float4 stdv;
    stdv.x = sqrtf(fmaxf(sqm.x - mean.x * mean.x, 1e-6f));
    stdv.y = sqrtf(fmaxf(sqm.y - mean.y * mean.y, 1e-6f));
    stdv.z = sqrtf(fmaxf(sqm.z - mean.z * mean.z, 1e-6f));
    stdv.w = sqrtf(fmaxf(sqm.w - mean.w * mean.w, 1e-6f));

    float sS = __ldg(g_scaleS + gw);
    float facs[3] = {1.0f, sS, 1.0f / fmaxf(sS, 1e-2f)};
    int sub = lane >> 3;
    int off = 4 * (lane & 7);

    auto stv = [&](int f, const float4& v) {
#pragma unroll
        for (int j = 0; j < 3; j++) {
            float fac = facs[j];
            __half2 lo = __floats2half2_rn(v.x * fac, v.y * fac);
            __half2 hi = __floats2half2_rn(v.z * fac, v.w * fac);
            int ch = (j * 4 + f) * 4 + sub;
            *reinterpret_cast<uint2*>(g_Ah + ((size_t)ch * N_NODES + gw) * 32 + off) =
                make_uint2(*reinterpret_cast<uint32_t*>(&lo),
                           *reinterpret_cast<uint32_t*>(&hi));
        }
    };
    stv(0, mean); stv(1, vmx); stv(2, vmn); stv(3, stdv);
}

// ---------------- fp16 tensor-core GEMM + LN + ReLU + residual --------------
// Pure cp.async pipeline: A from g_Ah (chunk-major half), B from g_Wth.
// 4 stages, 128x128 block tile, 8 warps (2x4), mma.m16n8k16.f16, fp32 accum.
__global__ void __launch_bounds__(256, 2)
k_gemm(const __half* __restrict__ Wt, const float* __restrict__ bias,
       const float* __restrict__ lng, const float* __restrict__ lnb,
       const float* __restrict__ xin) {
    extern __shared__ __align__(16) char dynsm[];
    __shared__ float redS[128][4];
    __shared__ float redQ[128][4];

    uint32_t smA0 = (uint32_t)__cvta_generic_to_shared(dynsm);
    uint32_t smB0 = smA0 + NSTG * TILEB;

    int tid  = threadIdx.x;
    int lane = tid & 31, wid = tid >> 5;
    int wm = wid & 1, wn = wid >> 1;      // warp grid 2(m) x 4(n)
    int q = lane >> 2, p = lane & 3;
    int lrow = lane & 7;
    int lb3  = (lane >> 3) & 1;
    int lb4  = (lane >> 4) & 1;
    int row0 = blockIdx.x * 128;

    int lrw  = tid >> 1;                  // loader row (A and B)
    int lhf  = tid & 1;                   // loader half (two 32B segments)
    int grow = row0 + lrw;
    bool rok = grow < N_NODES;

    float acc[4][4][4];
#pragma unroll
    for (int i = 0; i < 4; i++)
#pragma unroll
        for (int j = 0; j < 4; j++)
#pragma unroll
            for (int c = 0; c < 4; c++) acc[i][j][c] = 0.0f;

    auto issueTile = [&](int kt) {
        int buf = kt & (NSTG - 1);
        if (rok) {
            const __half* srcA = g_Ah + ((size_t)kt * N_NODES + grow) * 32 + lhf * 16;
            uint32_t dA = smA0 + buf * TILEB + lrw * 80 + lhf * 32;
            asm volatile("cp.async.ca.shared.global [%0], [%1], 16;\n"
                         :: "r"(dA), "l"(srcA));
            asm volatile("cp.async.ca.shared.global [%0], [%1], 16;\n"
                         :: "r"(dA + 16), "l"(srcA + 8));
        }
        const __half* srcB = Wt + (size_t)lrw * KDIM + kt * BK + lhf * 16;
        uint32_t dB = smB0 + buf * TILEB + lrw * 80 + lhf * 32;
        asm volatile("cp.async.ca.shared.global [%0], [%1], 16;\n"
                     :: "r"(dB), "l"(srcB));
        asm volatile("cp.async.ca.shared.global [%0], [%1], 16;\n"
                     :: "r"(dB + 16), "l"(srcB + 8));
        asm volatile("cp.async.commit_group;\n");
    };

    // prologue: fill 3 stages
    issueTile(0);
    issueTile(1);
    issueTile(2);

#pragma unroll 1
    for (int kt = 0; kt < NKT; kt++) {
        int buf = kt & (NSTG - 1);
        int ahead = NKT - 1 - kt;
        if (ahead > 2) {
            asm volatile("cp.async.wait_group 2;\n");
        } else if (ahead == 2) {
            asm volatile("cp.async.wait_group 2;\n");
        } else if (ahead == 1) {
            asm volatile("cp.async.wait_group 1;\n");
        } else {
            asm volatile("cp.async.wait_group 0;\n");
        }
        __syncthreads();
        if (kt + 3 < NKT) issueTile(kt + 3);

        uint32_t Abase = smA0 + buf * TILEB;
        uint32_t Bbase = smB0 + buf * TILEB;

#pragma unroll
        for (int kk = 0; kk < 2; kk++) {
            uint32_t a[4][4], b[2][4];
#pragma unroll
            for (int mt = 0; mt < 4; mt++) {
                int ar = wm * 64 + mt * 16 + lrow + lb3 * 8;
                int ac = kk * 16 + lb4 * 8;
                uint32_t addr = Abase + ar * 80 + ac * 2;
                asm volatile(
                    "ldmatrix.sync.aligned.m8n8.x4.shared.b16 {%0,%1,%2,%3}, [%4];"
                    : "=r"(a[mt][0]), "=r"(a[mt][1]), "=r"(a[mt][2]), "=r"(a[mt][3])
                    : "r"(addr));
            }
#pragma unroll
            for (int ntp = 0; ntp < 2; ntp++) {
                int br = wn * 32 + ntp * 16 + lrow + lb4 * 8;
                int bc = kk * 16 + lb3 * 8;
                uint32_t addr = Bbase + br * 80 + bc * 2;
                asm volatile(
                    "ldmatrix.sync.aligned.m8n8.x4.shared.b16 {%0,%1,%2,%3}, [%4];"
                    : "=r"(b[ntp][0]), "=r"(b[ntp][1]), "=r"(b[ntp][2]), "=r"(b[ntp][3])
                    : "r"(addr));
            }
#pragma unroll
            for (int mt = 0; mt < 4; mt++)
#pragma unroll
                for (int nt = 0; nt < 4; nt++) {
                    int ntp = nt >> 1, hh = (nt & 1) * 2;
                    asm volatile(
                        "mma.sync.aligned.m16n8k16.row.col.f32.f16.f16.f32 "
                        "{%0,%1,%2,%3}, {%4,%5,%6,%7}, {%8,%9}, {%0,%1,%2,%3};"
                        : "+f"(acc[mt][nt][0]), "+f"(acc[mt][nt][1]),
                          "+f"(acc[mt][nt][2]), "+f"(acc[mt][nt][3])
                        : "r"(a[mt][0]), "r"(a[mt][1]), "r"(a[mt][2]), "r"(a[mt][3]),
                          "r"(b[ntp][hh]), "r"(b[ntp][hh + 1]));
                }
        }
    }
    __syncthreads();

    // ---- epilogue: bias + LN + ReLU + residual (+ half x chunks for next layer)
    float2 bias2[4], lng2[4], lnb2[4];
#pragma unroll
    for (int nt = 0; nt < 4; nt++) {
        int c = wn * 32 + nt * 8 + 2 * p;
        bias2[nt] = *reinterpret_cast<const float2*>(bias + c);
        lng2[nt]  = *reinterpret_cast<const float2*>(lng + c);
        lnb2[nt]  = *reinterpret_cast<const float2*>(lnb + c);
    }

#pragma unroll
    for (int mt = 0; mt < 4; mt++) {
        float sA = 0.f, qA = 0.f, sB = 0.f, qB = 0.f;
#pragma unroll
        for (int nt = 0; nt < 4; nt++) {
            float v0 = acc[mt][nt][0] + bias2[nt].x;
            float v1 = acc[mt][nt][1] + bias2[nt].y;
            float v2 = acc[mt][nt][2] + bias2[nt].x;
            float v3 = acc[mt][nt][3] + bias2[nt].y;
            sA += v0 + v1; qA += v0 * v0 + v1 * v1;
            sB += v2 + v3; qB += v2 * v2 + v3 * v3;
        }
#pragma unroll
        for (int m = 1; m < 4; m <<= 1) {
            sA += __shfl_xor_sync(0xffffffffu, sA, m);
            qA += __shfl_xor_sync(0xffffffffu, qA, m);
            sB += __shfl_xor_sync(0xffffffffu, sB, m);
            qB += __shfl_xor_sync(0xffffffffu, qB, m);
        }
        if (p == 0) {
            int rA = wm * 64 + mt * 16 + q;
            redS[rA][wn] = sA; redQ[rA][wn] = qA;
            redS[rA + 8][wn] = sB; redQ[rA + 8][wn] = qB;
        }
    }
    __syncthreads();

#pragma unroll
    for (int mt = 0; mt < 4; mt++) {
#pragma unroll
        for (int half = 0; half < 2; half++) {
            int rloc = wm * 64 + mt * 16 + q + half * 8;
            int r = row0 + rloc;
            float s = redS[rloc][0] + redS[rloc][1] + redS[rloc][2] + redS[rloc][3];
            float sq = redQ[rloc][0] + redQ[rloc][1] + redQ[rloc][2] + redQ[rloc][3];
            float mu = s * (1.0f / 128.0f);
            float var = sq * (1.0f / 128.0f) - mu * mu;
            float rstd = rsqrtf(var + 1e-5f);
            if (r < N_NODES) {
#pragma unroll
                for (int nt = 0; nt < 4; nt++) {
                    int c = wn * 32 + nt * 8 + 2 * p;
                    float v0 = acc[mt][nt][half * 2 + 0] + bias2[nt].x;
                    float v1 = acc[mt][nt][half * 2 + 1] + bias2[nt].y;
                    float o0 = fmaxf((v0 - mu) * rstd * lng2[nt].x + lnb2[nt].x, 0.0f);
                    float o1 = fmaxf((v1 - mu) * rstd * lng2[nt].y + lnb2[nt].y, 0.0f);
                    float2 xr = *reinterpret_cast<const float2*>(xin + r * 128 + c);
                    float n0 = o0 + xr.x, n1 = o1 + xr.y;
                    *reinterpret_cast<float2*>(g_x + r * 128 + c) = make_float2(n0, n1);
                    // half copy into A chunks 48..51 for the next layer's GEMM
                    __half2 hx = __floats2half2_rn(n0, n1);
                    *reinterpret_cast<uint32_t*>(
                        g_Ah + ((size_t)(48 + wn) * N_NODES + r) * 32 + nt * 8 + 2 * p) =
                        *reinterpret_cast<uint32_t*>(&hx);
                }
            }
        }
    }
}

// ---------------- distmult scoring (warp per triple) ------------------------
__global__ void k_score(const int* __restrict__ src, const int* __restrict__ rel,
                        const int* __restrict__ dst, const float* __restrict__ qw,
                        float* __restrict__ out) {
    int gw   = (blockIdx.x * blockDim.x + threadIdx.x) >> 5;
    int lane = threadIdx.x & 31;
    if (gw >= 1024 * 32) return;
    int s = __ldg(src + gw), r = __ldg(rel + gw), d = __ldg(dst + gw);
    const float4* xv = reinterpret_cast<const float4*>(g_x);
    float4 a = __ldg(xv + s * 32 + lane);
    float4 qq = __ldg(reinterpret_cast<const float4*>(qw) + r * 32 + lane);
    float4 c = __ldg(xv + d * 32 + lane);
    float pr = a.x * qq.x * c.x + a.y * qq.y * c.y + a.z * qq.z * c.z + a.w * qq.w * c.w;
#pragma unroll
    for (int m = 16; m > 0; m >>= 1) pr += __shfl_xor_sync(0xffffffffu, pr, m);
    if (lane == 0) out[gw] = pr;
}

// ---------------- launcher ---------------------------------------------------
extern "C" void kernel_launch(void* const* d_in, const int* in_sizes, int n_in,
                              void* d_out, int out_size) {
    const float* x0    = (const float*)d_in[0];
    const int*   eidx  = (const int*)  d_in[1];
    const int*   etype = (const int*)  d_in[2];
    const float* ew    = (const float*)d_in[3];
    const float* relw  = (const float*)d_in[4];
    const float* linw  = (const float*)d_in[5];
    const float* linb  = (const float*)d_in[6];
    const float* lng   = (const float*)d_in[7];
    const float* lnb   = (const float*)d_in[8];
    const float* qw    = (const float*)d_in[9];
    const int*   src   = (const int*)  d_in[10];
    const int*   rel   = (const int*)  d_in[11];
    const int*   dst   = (const int*)  d_in[12];
    float*       out   = (float*)d_out;

    const int* esrc = eidx;
    const int* edst = eidx + N_EDGES;

    float*  gx;   cudaGetSymbolAddress((void**)&gx, g_x);
    __half* gWh;  cudaGetSymbolAddress((void**)&gWh, g_Wth);
    int*    gdeg; cudaGetSymbolAddress((void**)&gdeg, g_deg);

    static int attr_set = 0;
    if (!attr_set) {
        cudaFuncSetAttribute(k_gemm, cudaFuncAttributeMaxDynamicSharedMemorySize,
                             2 * NSTG * TILEB);
        attr_set = 1;
    }

    cudaMemsetAsync(gdeg, 0, N_NODES * sizeof(int));

    k_hist<<<(N_EDGES + 255) / 256, 256>>>(edst);
    k_scan<<<1, 1024>>>();
    k_fill<<<(N_EDGES + 255) / 256, 256>>>(esrc, edst, etype, ew);

    for (int l = 0; l < 4; l++) {
        const float* xin = (l == 0) ? x0 : gx;
        k_agg<<<(N_NODES * 32 + 255) / 256, 256>>>(xin, x0, relw + l * N_REL * DIM);
        if (l == 0) {
            k_cvtx<<<(N_NODES * 32 + 255) / 256, 256>>>(x0);
            k_cvtWth<<<dim3(KDIM / 32, DIM / 32, 4), dim3(32, 8)>>>(linw);
        }
        k_gemm<<<(N_NODES + 127) / 128, 256, 2 * NSTG * TILEB>>>(
            gWh + (size_t)l * DIM * KDIM,
            linb + l * DIM,
            lng + l * DIM,
            lnb + l * DIM,
            xin);
    }

    k_score<<<(1024 * 32 * 32 + 255) / 256, 256>>>(src, rel, dst, qw, out);
}

// round 11
// speedup vs baseline: 1.7344x; 1.0500x over previous
#include <cuda_runtime.h>
#include <cuda_fp16.h>
#include <stdint.h>
#include <math.h>

#define N_NODES 50000
#define N_EDGES 500000
#define DIM     128
#define N_REL   51
#define KDIM    1664   // 13*128
#define BK      32
#define NKT     (KDIM / BK)   // 52
#define NSTG    4
#define TILEB   10240          // bytes per operand per stage (128 rows * 80B)
#define NGRP    6250           // N_NODES / 8

// ---------------- scratch (device globals; no allocation allowed) ----------
__device__ int    g_deg[N_NODES];
__device__ int    g_off[N_NODES + 1];
__device__ int    g_fill[N_NODES];
__device__ int    g_epk[N_EDGES];     // packed src | (type<<17)
__device__ float  g_ew[N_EDGES];
__device__ float  g_scaleS[N_NODES];
__device__ float  g_x[N_NODES * DIM];
__device__ __half g_Ah[(size_t)NKT * N_NODES * 32];  // chunk-major half A matrix
__device__ __half g_Wth[4 * DIM * KDIM];             // transposed half weights [l][n][k]
__device__ __half g_relh[4 * N_REL * DIM];           // half rel weights

// ---------------- preprocessing kernels ------------------------------------
// transpose + round weights to half: g_Wth[l][n][k] = h(linw[l][k][n])
__global__ void k_cvtWth(const float* __restrict__ linw) {
    __shared__ float tile[32][33];
    int l = blockIdx.z;
    int k0 = blockIdx.x * 32, n0 = blockIdx.y * 32;
    const float* src = linw + l * KDIM * DIM;
#pragma unroll
    for (int r = 0; r < 4; r++) {
        int k = k0 + threadIdx.y + r * 8;
        tile[threadIdx.y + r * 8][threadIdx.x] = src[k * DIM + n0 + threadIdx.x];
    }
    __syncthreads();
    __half* dst = g_Wth + l * DIM * KDIM;
#pragma unroll
    for (int r = 0; r < 4; r++) {
        int n = n0 + threadIdx.y + r * 8;
        dst[n * KDIM + k0 + threadIdx.x] =
            __float2half_rn(tile[threadIdx.x][threadIdx.y + r * 8]);
    }
}

__global__ void k_cvtrel(const float* __restrict__ relw) {
    int i = blockIdx.x * blockDim.x + threadIdx.x;
    if (i < 4 * N_REL * DIM) g_relh[i] = __float2half_rn(relw[i]);
}

// convert x (fp32 row-major) into A chunks 48..51 (half)
__global__ void k_cvtx(const float* __restrict__ x) {
    int i = blockIdx.x * blockDim.x + threadIdx.x;   // over N*32 groups of 4 cols
    if (i >= N_NODES * 32) return;
    int n = i >> 5, g = i & 31;
    int col = g * 4;
    float4 v = __ldg(reinterpret_cast<const float4*>(x + n * 128) + g);
    int ch = 48 + (col >> 5);
    int off = col & 31;
    __half2 lo = __floats2half2_rn(v.x, v.y);
    __half2 hi = __floats2half2_rn(v.z, v.w);
    *reinterpret_cast<uint2*>(g_Ah + ((size_t)ch * N_NODES + n) * 32 + off) =
        make_uint2(*reinterpret_cast<uint32_t*>(&lo), *reinterpret_cast<uint32_t*>(&hi));
}

__global__ void k_hist(const int* __restrict__ edst) {
    int e = blockIdx.x * blockDim.x + threadIdx.x;
    if (e < N_EDGES) atomicAdd(&g_deg[edst[e]], 1);
}

// single block, 1024 threads; 8 elements per thread per chunk.
__global__ void k_scan() {
    __shared__ int   wsum[32];
    __shared__ int   carry_sh;
    __shared__ float fred[32];
    __shared__ float ssum_sh;
    int tid  = threadIdx.x;
    int lane = tid & 31, wid = tid >> 5;
    if (tid == 0) carry_sh = 0;
    __syncthreads();

    float ls = 0.0f;
#pragma unroll 1
    for (int c = 0; c < 7; c++) {
        int g = c * 1024 + tid;
        int v[8];
        int tsum = 0;
        if (g < NGRP) {
            int4 a = *reinterpret_cast<const int4*>(g_deg + g * 8);
            int4 b = *reinterpret_cast<const int4*>(g_deg + g * 8 + 4);
            v[0] = a.x; v[1] = a.y; v[2] = a.z; v[3] = a.w;
            v[4] = b.x; v[5] = b.y; v[6] = b.z; v[7] = b.w;
#pragma unroll
            for (int j = 0; j < 8; j++) tsum += v[j];
        } else {
#pragma unroll
            for (int j = 0; j < 8; j++) v[j] = 0;
        }
        int x = tsum;
#pragma unroll
        for (int off = 1; off < 32; off <<= 1) {
            int y = __shfl_up_sync(0xffffffffu, x, off);
            if (lane >= off) x += y;
        }
        if (lane == 31) wsum[wid] = x;
        __syncthreads();
        if (wid == 0) {
            int w = wsum[lane];
#pragma unroll
            for (int off = 1; off < 32; off <<= 1) {
                int y = __shfl_up_sync(0xffffffffu, w, off);
                if (lane >= off) w += y;
            }
            wsum[lane] = w;
        }
        __syncthreads();
        int wpre = (wid > 0) ? wsum[wid - 1] : 0;
        int excl = carry_sh + wpre + x - tsum;
        if (g < NGRP) {
            int run = excl;
#pragma unroll
            for (int j = 0; j < 8; j++) {
                g_off[g * 8 + j]  = run;
                g_fill[g * 8 + j] = run;
                run += v[j];
                ls += logf((float)v[j] + 1.0f);
            }
        }
        __syncthreads();
        if (tid == 1023) carry_sh += wsum[31];
        __syncthreads();
    }
    if (tid == 0) g_off[N_NODES] = N_EDGES;

#pragma unroll
    for (int m = 16; m > 0; m >>= 1) ls += __shfl_xor_sync(0xffffffffu, ls, m);
    if (lane == 0) fred[wid] = ls;
    __syncthreads();
    if (wid == 0) {
        float s = fred[lane];
#pragma unroll
        for (int m = 16; m > 0; m >>= 1) s += __shfl_xor_sync(0xffffffffu, s, m);
        if (lane == 0) ssum_sh = s;
    }
    __syncthreads();
    float inv_mean = (float)N_NODES / ssum_sh;
#pragma unroll 1
    for (int g = tid; g < NGRP; g += 1024) {
        int4 a = *reinterpret_cast<const int4*>(g_deg + g * 8);
        int4 b = *reinterpret_cast<const int4*>(g_deg + g * 8 + 4);
        float4 o0, o1;
        o0.x = logf((float)a.x + 1.0f) * inv_mean;
        o0.y = logf((float)a.y + 1.0f) * inv_mean;
        o0.z = logf((float)a.z + 1.0f) * inv_mean;
        o0.w = logf((float)a.w + 1.0f) * inv_mean;
        o1.x = logf((float)b.x + 1.0f) * inv_mean;
        o1.y = logf((float)b.y + 1.0f) * inv_mean;
        o1.z = logf((float)b.z + 1.0f) * inv_mean;
        o1.w = logf((float)b.w + 1.0f) * inv_mean;
        *reinterpret_cast<float4*>(g_scaleS + g * 8)     = o0;
        *reinterpret_cast<float4*>(g_scaleS + g * 8 + 4) = o1;
    }
}

__global__ void k_fill(const int* __restrict__ esrc, const int* __restrict__ edst,
                       const int* __restrict__ etype, const float* __restrict__ ew) {
    int e = blockIdx.x * blockDim.x + threadIdx.x;
    if (e >= N_EDGES) return;
    int d = edst[e];
    int p = atomicAdd(&g_fill[d], 1);
    g_epk[p] = esrc[e] | (etype[e] << 17);
    g_ew[p]  = ew[e];
}

// ---------------- per-layer aggregation (warp per node) --------------------
// gathers x rows in HALF from g_Ah chunks 48..51, rel rows from g_relh.
// writes the 12 scale*feat blocks as half into g_Ah chunks 0..47.
__global__ void k_agg(const float* __restrict__ x0, const __half* __restrict__ relh) {
    int gw   = (blockIdx.x * blockDim.x + threadIdx.x) >> 5;
    int lane = threadIdx.x & 31;
    if (gw >= N_NODES) return;
    int beg = g_off[gw], end = g_off[gw + 1];

    float4 vs  = make_float4(0.f, 0.f, 0.f, 0.f);
    float4 vq  = make_float4(0.f, 0.f, 0.f, 0.f);
    float4 vmx = make_float4(-INFINITY, -INFINITY, -INFINITY, -INFINITY);
    float4 vmn = make_float4( INFINITY,  INFINITY,  INFINITY,  INFINITY);

    // lane-specific bases: dim 4*lane lives in chunk 48+(lane>>3), offset 4*(lane&7)
    const __half* xh = g_Ah + ((size_t)(48 + (lane >> 3)) * N_NODES) * 32
                       + 4 * (lane & 7);
    const __half* rh = relh + lane * 4;

    auto edgeAcc = [&](uint2 xu, uint2 ru, float w) {
        __half2 xa = *reinterpret_cast<__half2*>(&xu.x);
        __half2 xb = *reinterpret_cast<__half2*>(&xu.y);
        __half2 ra = *reinterpret_cast<__half2*>(&ru.x);
        __half2 rb = *reinterpret_cast<__half2*>(&ru.y);
        float2 xf0 = __half22float2(xa), xf1 = __half22float2(xb);
        float2 rf0 = __half22float2(ra), rf1 = __half22float2(rb);
        float mx = xf0.x * rf0.x * w, my = xf0.y * rf0.y * w;
        float mz = xf1.x * rf1.x * w, mw = xf1.y * rf1.y * w;
        vs.x += mx; vs.y += my; vs.z += mz; vs.w += mw;
        vq.x += mx * mx; vq.y += my * my; vq.z += mz * mz; vq.w += mw * mw;
        vmx.x = fmaxf(vmx.x, mx); vmx.y = fmaxf(vmx.y, my);
        vmx.z = fmaxf(vmx.z, mz); vmx.w = fmaxf(vmx.w, mw);
        vmn.x = fminf(vmn.x, mx); vmn.y = fminf(vmn.y, my);
        vmn.z = fminf(vmn.z, mz); vmn.w = fminf(vmn.w, mw);
    };

    int e = beg;
    for (; e + 2 <= end; e += 2) {
        int   pk0 = __ldg(g_epk + e);
        int   pk1 = __ldg(g_epk + e + 1);
        float w0  = __ldg(g_ew + e);
        float w1  = __ldg(g_ew + e + 1);
        int s0 = pk0 & 0x1FFFF, t0 = pk0 >> 17;
        int s1 = pk1 & 0x1FFFF, t1 = pk1 >> 17;
        uint2 xu0 = __ldg(reinterpret_cast<const uint2*>(xh + (size_t)s0 * 32));
        uint2 ru0 = __ldg(reinterpret_cast<const uint2*>(rh + t0 * 128));
        uint2 xu1 = __ldg(reinterpret_cast<const uint2*>(xh + (size_t)s1 * 32));
        uint2 ru1 = __ldg(reinterpret_cast<const uint2*>(rh + t1 * 128));
        edgeAcc(xu0, ru0, w0);
        edgeAcc(xu1, ru1, w1);
    }
    if (e < end) {
        int   pk = __ldg(g_epk + e);
        float w  = __ldg(g_ew + e);
        int s = pk & 0x1FFFF, t = pk >> 17;
        uint2 xu = __ldg(reinterpret_cast<const uint2*>(xh + (size_t)s * 32));
        uint2 ru = __ldg(reinterpret_cast<const uint2*>(rh + t * 128));
        edgeAcc(xu, ru, w);
    }

    // boundary self-message: original x0, fp32
    float4 b = __ldg(reinterpret_cast<const float4*>(x0) + gw * 32 + lane);
    vs.x += b.x; vs.y += b.y; vs.z += b.z; vs.w += b.w;
    vq.x += b.x * b.x; vq.y += b.y * b.y; vq.z += b.z * b.z; vq.w += b.w * b.w;
    vmx.x = fmaxf(vmx.x, b.x); vmx.y = fmaxf(vmx.y, b.y);
    vmx.z = fmaxf(vmx.z, b.z); vmx.w = fmaxf(vmx.w, b.w);
    vmn.x = fminf(vmn.x, b.x); vmn.y = fminf(vmn.y, b.y);
    vmn.z = fminf(vmn.z, b.z); vmn.w = fminf(vmn.w, b.w);

    float dinv = 1.0f / ((float)(end - beg) + 1.0f);
    float4 mean = make_float4(vs.x * dinv, vs.y * dinv, vs.z * dinv, vs.w * dinv);
    float4 sqm  = make_float4(vq.x * dinv, vq.y * dinv, vq.z * dinv, vq.w * dinv);
    float4 stdv;
    stdv.x = sqrtf(fmaxf(sqm.x - mean.x * mean.x, 1e-6f));
    stdv.y = sqrtf(fmaxf(sqm.y - mean.y * mean.y, 1e-6f));
    stdv.z = sqrtf(fmaxf(sqm.z - mean.z * mean.z, 1e-6f));
    stdv.w = sqrtf(fmaxf(sqm.w - mean.w * mean.w, 1e-6f));

    float sS = __ldg(g_scaleS + gw);
    float facs[3] = {1.0f, sS, 1.0f / fmaxf(sS, 1e-2f)};
    int sub = lane >> 3;
    int off = 4 * (lane & 7);

    auto stv = [&](int f, const float4& v) {
#pragma unroll
        for (int j = 0; j < 3; j++) {
            float fac = facs[j];
            __half2 lo = __floats2half2_rn(v.x * fac, v.y * fac);
            __half2 hi = __floats2half2_rn(v.z * fac, v.w * fac);
            int ch = (j * 4 + f) * 4 + sub;
            *reinterpret_cast<uint2*>(g_Ah + ((size_t)ch * N_NODES + gw) * 32 + off) =
                make_uint2(*reinterpret_cast<uint32_t*>(&lo),
                           *reinterpret_cast<uint32_t*>(&hi));
        }
    };
    stv(0, mean); stv(1, vmx); stv(2, vmn); stv(3, stdv);
}

// ---------------- fp16 tensor-core GEMM + LN + ReLU + residual --------------
// Pure cp.async pipeline: A from g_Ah (chunk-major half), B from g_Wth.
// 4 stages, 128x128 block tile, 8 warps (2x4), mma.m16n8k16.f16, fp32 accum.
__global__ void __launch_bounds__(256, 2)
k_gemm(const __half* __restrict__ Wt, const float* __restrict__ bias,
       const float* __restrict__ lng, const float* __restrict__ lnb,
       const float* __restrict__ xin) {
    extern __shared__ __align__(16) char dynsm[];
    __shared__ float redS[128][4];
    __shared__ float redQ[128][4];

    uint32_t smA0 = (uint32_t)__cvta_generic_to_shared(dynsm);
    uint32_t smB0 = smA0 + NSTG * TILEB;

    int tid  = threadIdx.x;
    int lane = tid & 31, wid = tid >> 5;
    int wm = wid & 1, wn = wid >> 1;      // warp grid 2(m) x 4(n)
    int q = lane >> 2, p = lane & 3;
    int lrow = lane & 7;
    int lb3  = (lane >> 3) & 1;
    int lb4  = (lane >> 4) & 1;
    int row0 = blockIdx.x * 128;

    int lrw  = tid >> 1;                  // loader row (A and B)
    int lhf  = tid & 1;                   // loader half (two 32B segments)
    int grow = row0 + lrw;
    bool rok = grow < N_NODES;

    float acc[4][4][4];
#pragma unroll
    for (int i = 0; i < 4; i++)
#pragma unroll
        for (int j = 0; j < 4; j++)
#pragma unroll
            for (int c = 0; c < 4; c++) acc[i][j][c] = 0.0f;

    auto issueTile = [&](int kt) {
        int buf = kt & (NSTG - 1);
        if (rok) {
            const __half* srcA = g_Ah + ((size_t)kt * N_NODES + grow) * 32 + lhf * 16;
            uint32_t dA = smA0 + buf * TILEB + lrw * 80 + lhf * 32;
            asm volatile("cp.async.ca.shared.global [%0], [%1], 16;\n"
                         :: "r"(dA), "l"(srcA));
            asm volatile("cp.async.ca.shared.global [%0], [%1], 16;\n"
                         :: "r"(dA + 16), "l"(srcA + 8));
        }
        const __half* srcB = Wt + (size_t)lrw * KDIM + kt * BK + lhf * 16;
        uint32_t dB = smB0 + buf * TILEB + lrw * 80 + lhf * 32;
        asm volatile("cp.async.ca.shared.global [%0], [%1], 16;\n"
                     :: "r"(dB), "l"(srcB));
        asm volatile("cp.async.ca.shared.global [%0], [%1], 16;\n"
                     :: "r"(dB + 16), "l"(srcB + 8));
        asm volatile("cp.async.commit_group;\n");
    };

    // prologue: fill 3 stages
    issueTile(0);
    issueTile(1);
    issueTile(2);

#pragma unroll 1
    for (int kt = 0; kt < NKT; kt++) {
        int buf = kt & (NSTG - 1);
        int ahead = NKT - 1 - kt;
        if (ahead >= 2) {
            asm volatile("cp.async.wait_group 2;\n");
        } else if (ahead == 1) {
            asm volatile("cp.async.wait_group 1;\n");
        } else {
            asm volatile("cp.async.wait_group 0;\n");
        }
        __syncthreads();
        if (kt + 3 < NKT) issueTile(kt + 3);

        uint32_t Abase = smA0 + buf * TILEB;
        uint32_t Bbase = smB0 + buf * TILEB;

#pragma unroll
        for (int kk = 0; kk < 2; kk++) {
            uint32_t a[4][4], b[2][4];
#pragma unroll
            for (int mt = 0; mt < 4; mt++) {
                int ar = wm * 64 + mt * 16 + lrow + lb3 * 8;
                int ac = kk * 16 + lb4 * 8;
                uint32_t addr = Abase + ar * 80 + ac * 2;
                asm volatile(
                    "ldmatrix.sync.aligned.m8n8.x4.shared.b16 {%0,%1,%2,%3}, [%4];"
                    : "=r"(a[mt][0]), "=r"(a[mt][1]), "=r"(a[mt][2]), "=r"(a[mt][3])
                    : "r"(addr));
            }
#pragma unroll
            for (int ntp = 0; ntp < 2; ntp++) {
                int br = wn * 32 + ntp * 16 + lrow + lb4 * 8;
                int bc = kk * 16 + lb3 * 8;
                uint32_t addr = Bbase + br * 80 + bc * 2;
                asm volatile(
                    "ldmatrix.sync.aligned.m8n8.x4.shared.b16 {%0,%1,%2,%3}, [%4];"
                    : "=r"(b[ntp][0]), "=r"(b[ntp][1]), "=r"(b[ntp][2]), "=r"(b[ntp][3])
                    : "r"(addr));
            }
#pragma unroll
            for (int mt = 0; mt < 4; mt++)
#pragma unroll
                for (int nt = 0; nt < 4; nt++) {
                    int ntp = nt >> 1, hh = (nt & 1) * 2;
                    asm volatile(
                        "mma.sync.aligned.m16n8k16.row.col.f32.f16.f16.f32 "
                        "{%0,%1,%2,%3}, {%4,%5,%6,%7}, {%8,%9}, {%0,%1,%2,%3};"
                        : "+f"(acc[mt][nt][0]), "+f"(acc[mt][nt][1]),
                          "+f"(acc[mt][nt][2]), "+f"(acc[mt][nt][3])
                        : "r"(a[mt][0]), "r"(a[mt][1]), "r"(a[mt][2]), "r"(a[mt][3]),
                          "r"(b[ntp][hh]), "r"(b[ntp][hh + 1]));
                }
        }
    }
    __syncthreads();

    // ---- epilogue: bias + LN + ReLU + residual (+ half x chunks for next layer)
    float2 bias2[4], lng2[4], lnb2[4];
#pragma unroll
    for (int nt = 0; nt < 4; nt++) {
        int c = wn * 32 + nt * 8 + 2 * p;
        bias2[nt] = *reinterpret_cast<const float2*>(bias + c);
        lng2[nt]  = *reinterpret_cast<const float2*>(lng + c);
        lnb2[nt]  = *reinterpret_cast<const float2*>(lnb + c);
    }

#pragma unroll
    for (int mt = 0; mt < 4; mt++) {
        float sA = 0.f, qA = 0.f, sB = 0.f, qB = 0.f;
#pragma unroll
        for (int nt = 0; nt < 4; nt++) {
            float v0 = acc[mt][nt][0] + bias2[nt].x;
            float v1 = acc[mt][nt][1] + bias2[nt].y;
            float v2 = acc[mt][nt][2] + bias2[nt].x;
            float v3 = acc[mt][nt][3] + bias2[nt].y;
            sA += v0 + v1; qA += v0 * v0 + v1 * v1;
            sB += v2 + v3; qB += v2 * v2 + v3 * v3;
        }
#pragma unroll
        for (int m = 1; m < 4; m <<= 1) {
            sA += __shfl_xor_sync(0xffffffffu, sA, m);
            qA += __shfl_xor_sync(0xffffffffu, qA, m);
            sB += __shfl_xor_sync(0xffffffffu, sB, m);
            qB += __shfl_xor_sync(0xffffffffu, qB, m);
        }
        if (p == 0) {
            int rA = wm * 64 + mt * 16 + q;
            redS[rA][wn] = sA; redQ[rA][wn] = qA;
            redS[rA + 8][wn] = sB; redQ[rA + 8][wn] = qB;
        }
    }
    __syncthreads();

#pragma unroll
    for (int mt = 0; mt < 4; mt++) {
#pragma unroll
        for (int half = 0; half < 2; half++) {
            int rloc = wm * 64 + mt * 16 + q + half * 8;
            int r = row0 + rloc;
            float s = redS[rloc][0] + redS[rloc][1] + redS[rloc][2] + redS[rloc][3];
            float sq = redQ[rloc][0] + redQ[rloc][1] + redQ[rloc][2] + redQ[rloc][3];
            float mu = s * (1.0f / 128.0f);
            float var = sq * (1.0f / 128.0f) - mu * mu;
            float rstd = rsqrtf(var + 1e-5f);
            if (r < N_NODES) {
#pragma unroll
                for (int nt = 0; nt < 4; nt++) {
                    int c = wn * 32 + nt * 8 + 2 * p;
                    float v0 = acc[mt][nt][half * 2 + 0] + bias2[nt].x;
                    float v1 = acc[mt][nt][half * 2 + 1] + bias2[nt].y;
                    float o0 = fmaxf((v0 - mu) * rstd * lng2[nt].x + lnb2[nt].x, 0.0f);
                    float o1 = fmaxf((v1 - mu) * rstd * lng2[nt].y + lnb2[nt].y, 0.0f);
                    float2 xr = *reinterpret_cast<const float2*>(xin + r * 128 + c);
                    float n0 = o0 + xr.x, n1 = o1 + xr.y;
                    *reinterpret_cast<float2*>(g_x + r * 128 + c) = make_float2(n0, n1);
                    // half copy into A chunks 48..51 for the next layer
                    __half2 hx = __floats2half2_rn(n0, n1);
                    *reinterpret_cast<uint32_t*>(
                        g_Ah + ((size_t)(48 + wn) * N_NODES + r) * 32 + nt * 8 + 2 * p) =
                        *reinterpret_cast<uint32_t*>(&hx);
                }
            }
        }
    }
}

// ---------------- distmult scoring (warp per triple) ------------------------
__global__ void k_score(const int* __restrict__ src, const int* __restrict__ rel,
                        const int* __restrict__ dst, const float* __restrict__ qw,
                        float* __restrict__ out) {
    int gw   = (blockIdx.x * blockDim.x + threadIdx.x) >> 5;
    int lane = threadIdx.x & 31;
    if (gw >= 1024 * 32) return;
    int s = __ldg(src + gw), r = __ldg(rel + gw), d = __ldg(dst + gw);
    const float4* xv = reinterpret_cast<const float4*>(g_x);
    float4 a = __ldg(xv + s * 32 + lane);
    float4 qq = __ldg(reinterpret_cast<const float4*>(qw) + r * 32 + lane);
    float4 c = __ldg(xv + d * 32 + lane);
    float pr = a.x * qq.x * c.x + a.y * qq.y * c.y + a.z * qq.z * c.z + a.w * qq.w * c.w;
#pragma unroll
    for (int m = 16; m > 0; m >>= 1) pr += __shfl_xor_sync(0xffffffffu, pr, m);
    if (lane == 0) out[gw] = pr;
}

// ---------------- launcher ---------------------------------------------------
extern "C" void kernel_launch(void* const* d_in, const int* in_sizes, int n_in,
                              void* d_out, int out_size) {
    const float* x0    = (const float*)d_in[0];
    const int*   eidx  = (const int*)  d_in[1];
    const int*   etype = (const int*)  d_in[2];
    const float* ew    = (const float*)d_in[3];
    const float* relw  = (const float*)d_in[4];
    const float* linw  = (const float*)d_in[5];
    const float* linb  = (const float*)d_in[6];
    const float* lng   = (const float*)d_in[7];
    const float* lnb   = (const float*)d_in[8];
    const float* qw    = (const float*)d_in[9];
    const int*   src   = (const int*)  d_in[10];
    const int*   rel   = (const int*)  d_in[11];
    const int*   dst   = (const int*)  d_in[12];
    float*       out   = (float*)d_out;

    const int* esrc = eidx;
    const int* edst = eidx + N_EDGES;

    float*  gx;   cudaGetSymbolAddress((void**)&gx, g_x);
    __half* gWh;  cudaGetSymbolAddress((void**)&gWh, g_Wth);
    __half* grh;  cudaGetSymbolAddress((void**)&grh, g_relh);
    int*    gdeg; cudaGetSymbolAddress((void**)&gdeg, g_deg);

    static int attr_set = 0;
    if (!attr_set) {
        cudaFuncSetAttribute(k_gemm, cudaFuncAttributeMaxDynamicSharedMemorySize,
                             2 * NSTG * TILEB);
        attr_set = 1;
    }

    cudaMemsetAsync(gdeg, 0, N_NODES * sizeof(int));

    k_hist<<<(N_EDGES + 255) / 256, 256>>>(edst);
    k_scan<<<1, 1024>>>();
    k_fill<<<(N_EDGES + 255) / 256, 256>>>(esrc, edst, etype, ew);
    k_cvtx<<<(N_NODES * 32 + 255) / 256, 256>>>(x0);
    k_cvtWth<<<dim3(KDIM / 32, DIM / 32, 4), dim3(32, 8)>>>(linw);
    k_cvtrel<<<(4 * N_REL * DIM + 255) / 256, 256>>>(relw);

    for (int l = 0; l < 4; l++) {
        const float* xin = (l == 0) ? x0 : gx;
        k_agg<<<(N_NODES * 32 + 255) / 256, 256>>>(x0, grh + l * N_REL * DIM);
        k_gemm<<<(N_NODES + 127) / 128, 256, 2 * NSTG * TILEB>>>(
            gWh + (size_t)l * DIM * KDIM,
            linb + l * DIM,
            lng + l * DIM,
            lnb + l * DIM,
            xin);
    }

    k_score<<<(1024 * 32 * 32 + 255) / 256, 256>>>(src, rel, dst, qw, out);
}